// round 2
// baseline (speedup 1.0000x reference)
#include <cuda_runtime.h>
#include <math.h>

#define Nb  8
#define Lq  2048
#define Sk  2048
#define Ein 1024
#define Dh  64

// Scratch for projected q/k/v: 4 MB each (allocation-free rule -> device globals)
__device__ float g_qh[Nb * Lq * Dh];
__device__ float g_kh[Nb * Sk * Dh];
__device__ float g_vh[Nb * Sk * Dh];

// C[M,64] = A[M,1024] @ W[1024,64], 64x64 tile per block, 256 threads, 4x4 per thread
__global__ __launch_bounds__(256) void proj_kernel(const float* __restrict__ A,
                                                   const float* __restrict__ W,
                                                   float* __restrict__ C) {
    __shared__ float As[32][65];   // [kk][row]
    __shared__ float Ws[32][64];   // [kk][col]
    const int t  = threadIdx.x;
    const int tx = t & 15;
    const int ty = t >> 4;
    const int m0 = blockIdx.x * 64;

    float acc[4][4] = {};

    for (int k0 = 0; k0 < Ein; k0 += 32) {
#pragma unroll
        for (int i = 0; i < 8; i++) {
            int idx = t + i * 256;
            int r = idx >> 5, kk = idx & 31;
            As[kk][r] = A[(m0 + r) * Ein + k0 + kk];
        }
#pragma unroll
        for (int i = 0; i < 8; i++) {
            int idx = t + i * 256;
            int kk = idx >> 6, c = idx & 63;
            Ws[kk][c] = W[(k0 + kk) * Dh + c];
        }
        __syncthreads();
#pragma unroll
        for (int kk = 0; kk < 32; kk++) {
            float a[4], b[4];
#pragma unroll
            for (int i = 0; i < 4; i++) a[i] = As[kk][ty * 4 + i];
#pragma unroll
            for (int j = 0; j < 4; j++) b[j] = Ws[kk][tx * 4 + j];
#pragma unroll
            for (int i = 0; i < 4; i++)
#pragma unroll
                for (int j = 0; j < 4; j++)
                    acc[i][j] = fmaf(a[i], b[j], acc[i][j]);
        }
        __syncthreads();
    }
#pragma unroll
    for (int i = 0; i < 4; i++)
#pragma unroll
        for (int j = 0; j < 4; j++)
            C[(m0 + ty * 4 + i) * Dh + tx * 4 + j] = acc[i][j];
}

// Flash attention, fp32. Block = (batch n, 64-row q tile). 256 threads, 4x4 register tiles.
__global__ __launch_bounds__(256) void attn_kernel(float* __restrict__ out) {
    __shared__ float Qs[64][65];   // [d][row]
    __shared__ float Ks[64][65];   // [d][col j]
    __shared__ float Vs[64][65];   // [j][d]
    __shared__ float Ps[64][65];   // [j][row]

    const int t  = threadIdx.x;
    const int tx = t & 15;
    const int ty = t >> 4;
    const int n  = blockIdx.y;
    const int qt = (int)(gridDim.x - 1) - (int)blockIdx.x;  // heavy tiles first
    const int q0 = qt * 64;

    const float* __restrict__ qh = g_qh + n * Lq * Dh;
    const float* __restrict__ kh = g_kh + n * Sk * Dh;
    const float* __restrict__ vh = g_vh + n * Sk * Dh;

    for (int i = t; i < 64 * 64; i += 256) {
        int r = i >> 6, d = i & 63;
        Qs[d][r] = qh[(q0 + r) * Dh + d];
    }

    float o[4][4] = {};
    float m[4], l[4];
#pragma unroll
    for (int i = 0; i < 4; i++) { m[i] = -1e30f; l[i] = 0.0f; }

    for (int s0 = 0; s0 <= q0; s0 += 64) {
        __syncthreads();  // protect Ks/Vs/Ps of previous iteration (and Qs on first)
        for (int i = t; i < 64 * 64; i += 256) {
            int j = i >> 6, d = i & 63;
            Ks[d][j] = kh[(s0 + j) * Dh + d];
            Vs[j][d] = vh[(s0 + j) * Dh + d];
        }
        __syncthreads();

        // S = Q K^T over d (4x4 per thread)
        float s[4][4] = {};
#pragma unroll
        for (int d = 0; d < 64; d++) {
            float a[4], b[4];
#pragma unroll
            for (int i = 0; i < 4; i++) a[i] = Qs[d][ty * 4 + i];
#pragma unroll
            for (int j = 0; j < 4; j++) b[j] = Ks[d][tx * 4 + j];
#pragma unroll
            for (int i = 0; i < 4; i++)
#pragma unroll
                for (int j = 0; j < 4; j++)
                    s[i][j] = fmaf(a[i], b[j], s[i][j]);
        }

        const bool diag = (s0 == q0);
#pragma unroll
        for (int i = 0; i < 4; i++) {
            int gi = q0 + ty * 4 + i;
#pragma unroll
            for (int j = 0; j < 4; j++) {
                s[i][j] *= 8.0f;  // faithful bug: multiply by sqrt(D)
                if (diag && (s0 + tx * 4 + j) > gi) s[i][j] = -1e30f;
            }
        }

        // online softmax per row (16 threads/row group share via shfl within 16-lane halves)
#pragma unroll
        for (int i = 0; i < 4; i++) {
            float tm = fmaxf(fmaxf(s[i][0], s[i][1]), fmaxf(s[i][2], s[i][3]));
#pragma unroll
            for (int off = 8; off >= 1; off >>= 1)
                tm = fmaxf(tm, __shfl_xor_sync(0xffffffffu, tm, off));
            float mn  = fmaxf(m[i], tm);
            float fac = __expf(m[i] - mn);
            float ps  = 0.0f;
#pragma unroll
            for (int j = 0; j < 4; j++) {
                float p = __expf(s[i][j] - mn);
                s[i][j] = p;
                ps += p;
            }
#pragma unroll
            for (int off = 8; off >= 1; off >>= 1)
                ps += __shfl_xor_sync(0xffffffffu, ps, off);
            l[i] = l[i] * fac + ps;
            m[i] = mn;
#pragma unroll
            for (int j = 0; j < 4; j++) o[i][j] *= fac;
        }

        // stage P transposed: Ps[j][row]
#pragma unroll
        for (int i = 0; i < 4; i++)
#pragma unroll
            for (int j = 0; j < 4; j++)
                Ps[tx * 4 + j][ty * 4 + i] = s[i][j];
        __syncthreads();

        // O += P V  (4 rows x 4 d-cols per thread)
#pragma unroll
        for (int j = 0; j < 64; j++) {
            float a[4], b[4];
#pragma unroll
            for (int i = 0; i < 4; i++) a[i] = Ps[j][ty * 4 + i];
#pragma unroll
            for (int jd = 0; jd < 4; jd++) b[jd] = Vs[j][tx * 4 + jd];
#pragma unroll
            for (int i = 0; i < 4; i++)
#pragma unroll
                for (int jd = 0; jd < 4; jd++)
                    o[i][jd] = fmaf(a[i], b[jd], o[i][jd]);
        }
    }

#pragma unroll
    for (int i = 0; i < 4; i++) {
        float inv = 1.0f / l[i];
#pragma unroll
        for (int jd = 0; jd < 4; jd++)
            out[(n * Lq + q0 + ty * 4 + i) * Dh + tx * 4 + jd] = o[i][jd] * inv;
    }
}

extern "C" void kernel_launch(void* const* d_in, const int* in_sizes, int n_in,
                              void* d_out, int out_size) {
    const float* q  = (const float*)d_in[0];
    const float* k  = (const float*)d_in[1];
    const float* v  = (const float*)d_in[2];
    const float* Wq = (const float*)d_in[3];
    const float* Wk = (const float*)d_in[4];
    const float* Wv = (const float*)d_in[5];
    // d_in[6] = attn_mask: known causal, not read
    float* out = (float*)d_out;

    float *qh, *kh, *vh;
    cudaGetSymbolAddress((void**)&qh, g_qh);
    cudaGetSymbolAddress((void**)&kh, g_kh);
    cudaGetSymbolAddress((void**)&vh, g_vh);

    proj_kernel<<<(Nb * Lq) / 64, 256>>>(q, Wq, qh);
    proj_kernel<<<(Nb * Sk) / 64, 256>>>(k, Wk, kh);
    proj_kernel<<<(Nb * Sk) / 64, 256>>>(v, Wv, vh);

    dim3 grid(Lq / 64, Nb);
    attn_kernel<<<grid, 256>>>(out);
}

// round 5
// speedup vs baseline: 1.1272x; 1.1272x over previous
#include <cuda_runtime.h>
#include <cuda_bf16.h>
#include <cstdint>
#include <math.h>

#define Nb  8
#define Lq  2048
#define Sk  2048
#define Ein 1024
#define Dh  64

// fp32 scratch for projected q/k/v
__device__ float g_qh[Nb * Lq * Dh];
__device__ float g_kh[Nb * Sk * Dh];
__device__ float g_vh[Nb * Sk * Dh];

// ---------------------------------------------------------------- helpers
__device__ __forceinline__ uint32_t smem_u32(const void* p) {
    uint32_t a;
    asm("{ .reg .u64 t; cvta.to.shared.u64 t, %1; cvt.u32.u64 %0, t; }"
        : "=r"(a) : "l"(p));
    return a;
}

#define LDMATRIX_X4(r0, r1, r2, r3, addr)                                   \
    asm volatile("ldmatrix.sync.aligned.m8n8.x4.shared.b16 {%0,%1,%2,%3}, [%4];" \
                 : "=r"(r0), "=r"(r1), "=r"(r2), "=r"(r3) : "r"(addr))

#define MMA_BF16(c, a, b0, b1)                                              \
    asm volatile("mma.sync.aligned.m16n8k16.row.col.f32.bf16.bf16.f32 "     \
                 "{%0,%1,%2,%3}, {%4,%5,%6,%7}, {%8,%9}, {%0,%1,%2,%3};"    \
                 : "+f"((c)[0]), "+f"((c)[1]), "+f"((c)[2]), "+f"((c)[3])   \
                 : "r"((a)[0]), "r"((a)[1]), "r"((a)[2]), "r"((a)[3]),      \
                   "r"(b0), "r"(b1))

// ---------------------------------------------------------------- projection GEMM
// C[M,64] = A[M,1024] @ W[1024,64], bf16 2-split x 2-split (4 products), fp32 accum.
// CTA tile 128x64, 8 warps in 4(m) x 2(n), warp tile 32x32. kb = 32.
#define KB    32
#define APAD  40   // 32 + 8 elements; 80B row stride (odd multiple of 16B)

__global__ __launch_bounds__(256) void proj_mma(
    const float* __restrict__ q,  const float* __restrict__ kk_,
    const float* __restrict__ v,
    const float* __restrict__ Wq, const float* __restrict__ Wk,
    const float* __restrict__ Wv,
    float* __restrict__ qh, float* __restrict__ kh, float* __restrict__ vh) {

    __shared__ __nv_bfloat16 Asm[2][128][APAD];
    __shared__ __nv_bfloat16 Wsm[2][64][APAD];

    const float* A; const float* W; float* C;
    if (blockIdx.y == 0)      { A = q;   W = Wq; C = qh; }
    else if (blockIdx.y == 1) { A = kk_; W = Wk; C = kh; }
    else                      { A = v;   W = Wv; C = vh; }

    const int t    = threadIdx.x;
    const int lane = t & 31;
    const int warp = t >> 5;
    const int wm   = warp >> 1;        // 0..3 -> m offset wm*32
    const int wn   = warp & 1;         // 0..1 -> n offset wn*32
    const int m0   = blockIdx.x * 128;

    float c[2][4][4] = {};             // [mi][ni][4]

    const uint32_t a_base = smem_u32(Asm);
    const uint32_t w_base = smem_u32(Wsm);

    // per-lane ldmatrix addresses (byte offsets computed once per k-step below)
    const int a_row = wm * 32 + (lane & 7) + ((lane >> 3) & 1) * 8;   // + mi*16
    const int a_colb = (lane >> 4) * 8;                                // + ks*16
    const int b_row = wn * 32 + (lane & 7) + ((lane >> 4) & 1) * 8;   // + g*16
    const int b_colb = ((lane >> 3) & 1) * 8;                          // + ks*16

    // gmem load assignments
    const int ar  = t >> 1;                 // A row 0..127
    const int ac  = (t & 1) * 16;           // A col base
    const int wkk = t >> 3;                 // W k row 0..31
    const int wnb = (t & 7) * 8;            // W n base

    for (int k0 = 0; k0 < Ein; k0 += KB) {
        // ---- load + split A tile [128][32]
        {
            const float4* src = (const float4*)(A + (size_t)(m0 + ar) * Ein + k0 + ac);
#pragma unroll
            for (int i = 0; i < 4; i++) {
                float4 p = src[i];
                float x[4] = {p.x, p.y, p.z, p.w};
#pragma unroll
                for (int e = 0; e < 4; e++) {
                    __nv_bfloat16 h = __float2bfloat16(x[e]);
                    __nv_bfloat16 l = __float2bfloat16(x[e] - __bfloat162float(h));
                    Asm[0][ar][ac + i * 4 + e] = h;
                    Asm[1][ar][ac + i * 4 + e] = l;
                }
            }
        }
        // ---- load + split W tile [32][64] -> transposed [n][k]
        {
            const float4* src = (const float4*)(W + (size_t)(k0 + wkk) * Dh + wnb);
#pragma unroll
            for (int i = 0; i < 2; i++) {
                float4 p = src[i];
                float x[4] = {p.x, p.y, p.z, p.w};
#pragma unroll
                for (int e = 0; e < 4; e++) {
                    __nv_bfloat16 h = __float2bfloat16(x[e]);
                    __nv_bfloat16 l = __float2bfloat16(x[e] - __bfloat162float(h));
                    Wsm[0][wnb + i * 4 + e][wkk] = h;
                    Wsm[1][wnb + i * 4 + e][wkk] = l;
                }
            }
        }
        __syncthreads();

#pragma unroll
        for (int ks = 0; ks < 2; ks++) {
            uint32_t af[2][2][4];   // [split][mi][4]
            uint32_t bf[2][2][4];   // [split][g: n-halves][4] -> frags (g,0)={0,1},(g,1)={2,3}
#pragma unroll
            for (int s = 0; s < 2; s++) {
#pragma unroll
                for (int mi = 0; mi < 2; mi++) {
                    uint32_t addr = a_base +
                        (uint32_t)(((s * 128 + a_row + mi * 16) * APAD) + ks * 16 + a_colb) * 2u;
                    LDMATRIX_X4(af[s][mi][0], af[s][mi][1], af[s][mi][2], af[s][mi][3], addr);
                }
#pragma unroll
                for (int g = 0; g < 2; g++) {
                    uint32_t addr = w_base +
                        (uint32_t)(((s * 64 + b_row + g * 16) * APAD) + ks * 16 + b_colb) * 2u;
                    LDMATRIX_X4(bf[s][g][0], bf[s][g][1], bf[s][g][2], bf[s][g][3], addr);
                }
            }
#pragma unroll
            for (int sa = 0; sa < 2; sa++)
#pragma unroll
                for (int sb = 0; sb < 2; sb++)
#pragma unroll
                    for (int mi = 0; mi < 2; mi++)
#pragma unroll
                        for (int ni = 0; ni < 4; ni++) {
                            int g = ni >> 1, h = ni & 1;
                            MMA_BF16(c[mi][ni], af[sa][mi],
                                     bf[sb][g][h * 2], bf[sb][g][h * 2 + 1]);
                        }
        }
        __syncthreads();
    }

    // ---- epilogue
#pragma unroll
    for (int mi = 0; mi < 2; mi++) {
#pragma unroll
        for (int ni = 0; ni < 4; ni++) {
            int row = m0 + wm * 32 + mi * 16 + (lane >> 2);
            int col = wn * 32 + ni * 8 + (lane & 3) * 2;
            float2 v0 = {c[mi][ni][0], c[mi][ni][1]};
            float2 v1 = {c[mi][ni][2], c[mi][ni][3]};
            *(float2*)(C + (size_t)row * Dh + col)       = v0;
            *(float2*)(C + (size_t)(row + 8) * Dh + col) = v1;
        }
    }
}

// ---------------------------------------------------------------- attention (fp32, known good)
__global__ __launch_bounds__(256) void attn_kernel(float* __restrict__ out) {
    __shared__ float Qs[64][65];
    __shared__ float Ks[64][65];
    __shared__ float Vs[64][65];
    __shared__ float Ps[64][65];

    const int t  = threadIdx.x;
    const int tx = t & 15;
    const int ty = t >> 4;
    const int n  = blockIdx.y;
    const int qt = (int)(gridDim.x - 1) - (int)blockIdx.x;
    const int q0 = qt * 64;

    const float* __restrict__ qh = g_qh + n * Lq * Dh;
    const float* __restrict__ kh = g_kh + n * Sk * Dh;
    const float* __restrict__ vh = g_vh + n * Sk * Dh;

    for (int i = t; i < 64 * 64; i += 256) {
        int r = i >> 6, d = i & 63;
        Qs[d][r] = qh[(q0 + r) * Dh + d];
    }

    float o[4][4] = {};
    float m[4], l[4];
#pragma unroll
    for (int i = 0; i < 4; i++) { m[i] = -1e30f; l[i] = 0.0f; }

    for (int s0 = 0; s0 <= q0; s0 += 64) {
        __syncthreads();
        for (int i = t; i < 64 * 64; i += 256) {
            int j = i >> 6, d = i & 63;
            Ks[d][j] = kh[(s0 + j) * Dh + d];
            Vs[j][d] = vh[(s0 + j) * Dh + d];
        }
        __syncthreads();

        float s[4][4] = {};
#pragma unroll
        for (int d = 0; d < 64; d++) {
            float a[4], b[4];
#pragma unroll
            for (int i = 0; i < 4; i++) a[i] = Qs[d][ty * 4 + i];
#pragma unroll
            for (int j = 0; j < 4; j++) b[j] = Ks[d][tx * 4 + j];
#pragma unroll
            for (int i = 0; i < 4; i++)
#pragma unroll
                for (int j = 0; j < 4; j++)
                    s[i][j] = fmaf(a[i], b[j], s[i][j]);
        }

        const bool diag = (s0 == q0);
#pragma unroll
        for (int i = 0; i < 4; i++) {
            int gi = q0 + ty * 4 + i;
#pragma unroll
            for (int j = 0; j < 4; j++) {
                s[i][j] *= 8.0f;
                if (diag && (s0 + tx * 4 + j) > gi) s[i][j] = -1e30f;
            }
        }

#pragma unroll
        for (int i = 0; i < 4; i++) {
            float tm = fmaxf(fmaxf(s[i][0], s[i][1]), fmaxf(s[i][2], s[i][3]));
#pragma unroll
            for (int off = 8; off >= 1; off >>= 1)
                tm = fmaxf(tm, __shfl_xor_sync(0xffffffffu, tm, off));
            float mn  = fmaxf(m[i], tm);
            float fac = __expf(m[i] - mn);
            float ps  = 0.0f;
#pragma unroll
            for (int j = 0; j < 4; j++) {
                float p = __expf(s[i][j] - mn);
                s[i][j] = p;
                ps += p;
            }
#pragma unroll
            for (int off = 8; off >= 1; off >>= 1)
                ps += __shfl_xor_sync(0xffffffffu, ps, off);
            l[i] = l[i] * fac + ps;
            m[i] = mn;
#pragma unroll
            for (int j = 0; j < 4; j++) o[i][j] *= fac;
        }

#pragma unroll
        for (int i = 0; i < 4; i++)
#pragma unroll
            for (int j = 0; j < 4; j++)
                Ps[tx * 4 + j][ty * 4 + i] = s[i][j];
        __syncthreads();

#pragma unroll
        for (int j = 0; j < 64; j++) {
            float a[4], b[4];
#pragma unroll
            for (int i = 0; i < 4; i++) a[i] = Ps[j][ty * 4 + i];
#pragma unroll
            for (int jd = 0; jd < 4; jd++) b[jd] = Vs[j][tx * 4 + jd];
#pragma unroll
            for (int i = 0; i < 4; i++)
#pragma unroll
                for (int jd = 0; jd < 4; jd++)
                    o[i][jd] = fmaf(a[i], b[jd], o[i][jd]);
        }
    }

#pragma unroll
    for (int i = 0; i < 4; i++) {
        float inv = 1.0f / l[i];
#pragma unroll
        for (int jd = 0; jd < 4; jd++)
            out[(n * Lq + q0 + ty * 4 + i) * Dh + tx * 4 + jd] = o[i][jd] * inv;
    }
}

extern "C" void kernel_launch(void* const* d_in, const int* in_sizes, int n_in,
                              void* d_out, int out_size) {
    const float* q  = (const float*)d_in[0];
    const float* k  = (const float*)d_in[1];
    const float* v  = (const float*)d_in[2];
    const float* Wq = (const float*)d_in[3];
    const float* Wk = (const float*)d_in[4];
    const float* Wv = (const float*)d_in[5];
    float* out = (float*)d_out;

    float *qh, *kh, *vh;
    cudaGetSymbolAddress((void**)&qh, g_qh);
    cudaGetSymbolAddress((void**)&kh, g_kh);
    cudaGetSymbolAddress((void**)&vh, g_vh);

    dim3 pgrid((Nb * Lq) / 128, 3);
    proj_mma<<<pgrid, 256>>>(q, k, v, Wq, Wk, Wv, qh, kh, vh);

    dim3 grid(Lq / 64, Nb);
    attn_kernel<<<grid, 256>>>(out);
}

// round 6
// speedup vs baseline: 1.9593x; 1.7382x over previous
#include <cuda_runtime.h>
#include <cuda_bf16.h>
#include <cstdint>
#include <math.h>

#define Nb  8
#define Lq  2048
#define Sk  2048
#define Ein 1024
#define Dh  64

// Q projected, fp32 (source for 3-way split in attention)
__device__ float g_qh[Nb * Lq * Dh];
// K projected, 3 bf16 split planes; V projected, 2 bf16 split planes
__device__ __nv_bfloat16 g_khh[Nb * Sk * Dh];
__device__ __nv_bfloat16 g_khm[Nb * Sk * Dh];
__device__ __nv_bfloat16 g_khl[Nb * Sk * Dh];
__device__ __nv_bfloat16 g_vhh[Nb * Sk * Dh];
__device__ __nv_bfloat16 g_vhl[Nb * Sk * Dh];

// ---------------------------------------------------------------- helpers
__device__ __forceinline__ uint32_t smem_u32(const void* p) {
    uint32_t a;
    asm("{ .reg .u64 t; cvta.to.shared.u64 t, %1; cvt.u32.u64 %0, t; }"
        : "=r"(a) : "l"(p));
    return a;
}
__device__ __forceinline__ float ex2f(float x) {
    float y; asm("ex2.approx.f32 %0, %1;" : "=f"(y) : "f"(x)); return y;
}

#define LDMATRIX_X4(r0, r1, r2, r3, addr)                                   \
    asm volatile("ldmatrix.sync.aligned.m8n8.x4.shared.b16 {%0,%1,%2,%3}, [%4];" \
                 : "=r"(r0), "=r"(r1), "=r"(r2), "=r"(r3) : "r"(addr))
#define LDMATRIX_X4_T(r0, r1, r2, r3, addr)                                 \
    asm volatile("ldmatrix.sync.aligned.m8n8.x4.trans.shared.b16 {%0,%1,%2,%3}, [%4];" \
                 : "=r"(r0), "=r"(r1), "=r"(r2), "=r"(r3) : "r"(addr))

#define MMA_BF16(c, a, b0, b1)                                              \
    asm volatile("mma.sync.aligned.m16n8k16.row.col.f32.bf16.bf16.f32 "     \
                 "{%0,%1,%2,%3}, {%4,%5,%6,%7}, {%8,%9}, {%0,%1,%2,%3};"    \
                 : "+f"((c)[0]), "+f"((c)[1]), "+f"((c)[2]), "+f"((c)[3])   \
                 : "r"((a)[0]), "r"((a)[1]), "r"((a)[2]), "r"((a)[3]),      \
                   "r"(b0), "r"(b1))

#define CP_ASYNC16(dst, src)                                                \
    asm volatile("cp.async.cg.shared.global [%0], [%1], 16;"                \
                 :: "r"(dst), "l"(src) : "memory")
#define CP_COMMIT()  asm volatile("cp.async.commit_group;" ::: "memory")
#define CP_WAIT1()   asm volatile("cp.async.wait_group 1;" ::: "memory")

#define PACK_BF16X2(u, x0, x1) \
    asm("cvt.rn.bf16x2.f32 %0, %1, %2;" : "=r"(u) : "f"(x1), "f"(x0))
__device__ __forceinline__ float bf_lo(uint32_t u) { return __uint_as_float(u << 16); }
__device__ __forceinline__ float bf_hi(uint32_t u) { return __uint_as_float(u & 0xffff0000u); }

// ---------------------------------------------------------------- projection GEMM
// C[M,64] = A[M,1024] @ W[1024,64], bf16 2x2-split, fp32 accum.
// CTA tile 128x64, 8 warps (4m x 2n), warp tile 32x32, kb=32, reg prefetch.
#define KB    32
#define APAD  40

__global__ __launch_bounds__(256) void proj_mma(
    const float* __restrict__ q,  const float* __restrict__ kk_,
    const float* __restrict__ v,
    const float* __restrict__ Wq, const float* __restrict__ Wk,
    const float* __restrict__ Wv,
    float* __restrict__ qh) {

    __shared__ __nv_bfloat16 Asm[2][128][APAD];
    __shared__ __nv_bfloat16 Wsm[2][64][APAD];

    const float* A; const float* W;
    if (blockIdx.y == 0)      { A = q;   W = Wq; }
    else if (blockIdx.y == 1) { A = kk_; W = Wk; }
    else                      { A = v;   W = Wv; }

    const int t    = threadIdx.x;
    const int lane = t & 31;
    const int warp = t >> 5;
    const int wm   = warp >> 1;
    const int wn   = warp & 1;
    const int m0   = blockIdx.x * 128;

    float c[2][4][4] = {};

    const uint32_t a_base = smem_u32(Asm);
    const uint32_t w_base = smem_u32(Wsm);

    const int a_row  = wm * 32 + (lane & 7) + ((lane >> 3) & 1) * 8;
    const int a_colb = (lane >> 4) * 8;
    const int b_row  = wn * 32 + (lane & 7) + ((lane >> 4) & 1) * 8;
    const int b_colb = ((lane >> 3) & 1) * 8;

    const int ar  = t >> 1;
    const int ac  = (t & 1) * 16;
    const int wkk = t >> 3;
    const int wnb = (t & 7) * 8;

    float4 pa[4], pw[2];
    {
        const float4* srcA = (const float4*)(A + (size_t)(m0 + ar) * Ein + ac);
#pragma unroll
        for (int i = 0; i < 4; i++) pa[i] = srcA[i];
        const float4* srcW = (const float4*)(W + (size_t)wkk * Dh + wnb);
#pragma unroll
        for (int i = 0; i < 2; i++) pw[i] = srcW[i];
    }

    for (int k0 = 0; k0 < Ein; k0 += KB) {
        // convert prefetched regs -> smem split planes
#pragma unroll
        for (int i = 0; i < 4; i++) {
            float x[4] = {pa[i].x, pa[i].y, pa[i].z, pa[i].w};
#pragma unroll
            for (int e = 0; e < 4; e++) {
                __nv_bfloat16 h = __float2bfloat16(x[e]);
                __nv_bfloat16 l = __float2bfloat16(x[e] - __bfloat162float(h));
                Asm[0][ar][ac + i * 4 + e] = h;
                Asm[1][ar][ac + i * 4 + e] = l;
            }
        }
#pragma unroll
        for (int i = 0; i < 2; i++) {
            float x[4] = {pw[i].x, pw[i].y, pw[i].z, pw[i].w};
#pragma unroll
            for (int e = 0; e < 4; e++) {
                __nv_bfloat16 h = __float2bfloat16(x[e]);
                __nv_bfloat16 l = __float2bfloat16(x[e] - __bfloat162float(h));
                Wsm[0][wnb + i * 4 + e][wkk] = h;
                Wsm[1][wnb + i * 4 + e][wkk] = l;
            }
        }
        __syncthreads();

        // prefetch next k tile (overlaps with mma below)
        if (k0 + KB < Ein) {
            const float4* srcA = (const float4*)(A + (size_t)(m0 + ar) * Ein + k0 + KB + ac);
#pragma unroll
            for (int i = 0; i < 4; i++) pa[i] = srcA[i];
            const float4* srcW = (const float4*)(W + (size_t)(k0 + KB + wkk) * Dh + wnb);
#pragma unroll
            for (int i = 0; i < 2; i++) pw[i] = srcW[i];
        }

#pragma unroll
        for (int ks = 0; ks < 2; ks++) {
            uint32_t af[2][2][4];
            uint32_t bf[2][2][4];
#pragma unroll
            for (int s = 0; s < 2; s++) {
#pragma unroll
                for (int mi = 0; mi < 2; mi++) {
                    uint32_t addr = a_base +
                        (uint32_t)(((s * 128 + a_row + mi * 16) * APAD) + ks * 16 + a_colb) * 2u;
                    LDMATRIX_X4(af[s][mi][0], af[s][mi][1], af[s][mi][2], af[s][mi][3], addr);
                }
#pragma unroll
                for (int g = 0; g < 2; g++) {
                    uint32_t addr = w_base +
                        (uint32_t)(((s * 64 + b_row + g * 16) * APAD) + ks * 16 + b_colb) * 2u;
                    LDMATRIX_X4(bf[s][g][0], bf[s][g][1], bf[s][g][2], bf[s][g][3], addr);
                }
            }
#pragma unroll
            for (int sa = 0; sa < 2; sa++)
#pragma unroll
                for (int sb = 0; sb < 2; sb++)
#pragma unroll
                    for (int mi = 0; mi < 2; mi++)
#pragma unroll
                        for (int ni = 0; ni < 4; ni++) {
                            int g = ni >> 1, h = ni & 1;
                            MMA_BF16(c[mi][ni], af[sa][mi],
                                     bf[sb][g][h * 2], bf[sb][g][h * 2 + 1]);
                        }
        }
        __syncthreads();
    }

    // ---- epilogue: Q -> fp32; K -> 3 bf16 planes; V -> 2 bf16 planes
    const int y = blockIdx.y;
#pragma unroll
    for (int mi = 0; mi < 2; mi++) {
#pragma unroll
        for (int ni = 0; ni < 4; ni++) {
            int row = m0 + wm * 32 + mi * 16 + (lane >> 2);
            int col = wn * 32 + ni * 8 + (lane & 3) * 2;
            if (y == 0) {
                float2 v0 = {c[mi][ni][0], c[mi][ni][1]};
                float2 v1 = {c[mi][ni][2], c[mi][ni][3]};
                *(float2*)(qh + (size_t)row * Dh + col)       = v0;
                *(float2*)(qh + (size_t)(row + 8) * Dh + col) = v1;
            } else {
#pragma unroll
                for (int rr = 0; rr < 2; rr++) {
                    float x0 = c[mi][ni][rr * 2], x1 = c[mi][ni][rr * 2 + 1];
                    size_t off = (size_t)(row + rr * 8) * Dh + col;
                    uint32_t u0; PACK_BF16X2(u0, x0, x1);
                    float r0 = x0 - bf_lo(u0), r1 = x1 - bf_hi(u0);
                    uint32_t u1; PACK_BF16X2(u1, r0, r1);
                    if (y == 1) {
                        float s0 = r0 - bf_lo(u1), s1 = r1 - bf_hi(u1);
                        uint32_t u2; PACK_BF16X2(u2, s0, s1);
                        *(uint32_t*)(g_khh + off) = u0;
                        *(uint32_t*)(g_khm + off) = u1;
                        *(uint32_t*)(g_khl + off) = u2;
                    } else {
                        *(uint32_t*)(g_vhh + off) = u0;
                        *(uint32_t*)(g_vhl + off) = u1;
                    }
                }
            }
        }
    }
}

// ---------------------------------------------------------------- attention (mma.sync)
// CTA = 64 q rows, 4 warps (one m16 row-block each), KV tiles of 64.
// log2 domain softmax (scale 8*log2e folded into Q); per-warp tile skip.
#define STRIDE 72          // bf16 elems per smem row (64 data + 8 pad)
#define PLANE_B (64 * STRIDE * 2)
#define NPLANE 5           // Kh, Km, Kl, Vh, Vl

__global__ __launch_bounds__(128) void attn_mma(float* __restrict__ out) {
    extern __shared__ uint8_t dsm[];
    const int t    = threadIdx.x;
    const int lane = t & 31;
    const int warp = t >> 5;
    const int n    = blockIdx.y;
    const int qt   = 31 - (int)blockIdx.x;          // heavy tiles first
    const int q0   = qt * 64;
    const int ntile = qt + 1;

    const uint32_t smb = smem_u32(dsm);

    // ---- Q A-fragments: 3 splits x 4 k-steps x 4 regs, direct from gmem
    uint32_t qa[3][4][4];
    {
        const float* qbase = g_qh + (size_t)n * Lq * Dh;
        const int r = q0 + warp * 16 + (lane >> 2);
        const float sc = 11.54156036f;   // 8 * log2(e)
#pragma unroll
        for (int ks = 0; ks < 4; ks++)
#pragma unroll
            for (int hh = 0; hh < 2; hh++)
#pragma unroll
                for (int rr = 0; rr < 2; rr++) {
                    float2 x = *(const float2*)(qbase + (size_t)(r + rr * 8) * Dh +
                                                ks * 16 + (lane & 3) * 2 + hh * 8);
                    float x0 = x.x * sc, x1 = x.y * sc;
                    uint32_t u0; PACK_BF16X2(u0, x0, x1);
                    float r0 = x0 - bf_lo(u0), r1 = x1 - bf_hi(u0);
                    uint32_t u1; PACK_BF16X2(u1, r0, r1);
                    float s0 = r0 - bf_lo(u1), s1 = r1 - bf_hi(u1);
                    uint32_t u2; PACK_BF16X2(u2, s0, s1);
                    int ai = rr + hh * 2;
                    qa[0][ks][ai] = u0; qa[1][ks][ai] = u1; qa[2][ks][ai] = u2;
                }
    }

    const __nv_bfloat16* gp[NPLANE] = {
        g_khh + (size_t)n * Sk * Dh, g_khm + (size_t)n * Sk * Dh,
        g_khl + (size_t)n * Sk * Dh, g_vhh + (size_t)n * Sk * Dh,
        g_vhl + (size_t)n * Sk * Dh };

    // cp.async issue of one KV tile into buffer b
    auto issue_tile = [&](int tile, int b) {
#pragma unroll
        for (int i = 0; i < 4; i++) {
            int chunk = t + i * 128;            // 0..511
            int row = chunk >> 3, c16 = chunk & 7;
            uint32_t doff = (uint32_t)(row * STRIDE * 2 + c16 * 16);
            size_t goff = ((size_t)(tile * 64 + row) * Dh + c16 * 8);
#pragma unroll
            for (int p = 0; p < NPLANE; p++) {
                uint32_t dst = smb + (uint32_t)((b * NPLANE + p) * PLANE_B) + doff;
                CP_ASYNC16(dst, (const void*)(gp[p] + goff));
            }
        }
    };

    issue_tile(0, 0);
    CP_COMMIT();

    float O[8][4] = {};
    float m0 = -1e30f, m1 = -1e30f, l0 = 0.0f, l1 = 0.0f;

    for (int tile = 0; tile < ntile; tile++) {
        if (tile + 1 < ntile) issue_tile(tile + 1, (tile + 1) & 1);
        CP_COMMIT();
        CP_WAIT1();
        __syncthreads();

        const int b = tile & 1;
        const uint32_t kh_p = smb + (uint32_t)((b * NPLANE + 0) * PLANE_B);
        const uint32_t km_p = smb + (uint32_t)((b * NPLANE + 1) * PLANE_B);
        const uint32_t kl_p = smb + (uint32_t)((b * NPLANE + 2) * PLANE_B);
        const uint32_t vh_p = smb + (uint32_t)((b * NPLANE + 3) * PLANE_B);
        const uint32_t vl_p = smb + (uint32_t)((b * NPLANE + 4) * PLANE_B);

        // ---- S = Q K^T (6 split products)
        float S[8][4] = {};
        {
            const uint32_t koff =
                (uint32_t)(((lane & 7) + (lane >> 4) * 8) * STRIDE + ((lane >> 3) & 1) * 8) * 2u;
#pragma unroll
            for (int ks = 0; ks < 4; ks++)
#pragma unroll
                for (int sg = 0; sg < 4; sg++) {
                    uint32_t base = (uint32_t)(sg * 16 * STRIDE + ks * 16) * 2u + koff;
                    uint32_t kh[4], km[4], kl[4];
                    LDMATRIX_X4(kh[0], kh[1], kh[2], kh[3], kh_p + base);
                    LDMATRIX_X4(km[0], km[1], km[2], km[3], km_p + base);
                    LDMATRIX_X4(kl[0], kl[1], kl[2], kl[3], kl_p + base);
                    // products (qi, kj) with i+j<=2
                    MMA_BF16(S[2 * sg],     qa[0][ks], kh[0], kh[1]);
                    MMA_BF16(S[2 * sg + 1], qa[0][ks], kh[2], kh[3]);
                    MMA_BF16(S[2 * sg],     qa[0][ks], km[0], km[1]);
                    MMA_BF16(S[2 * sg + 1], qa[0][ks], km[2], km[3]);
                    MMA_BF16(S[2 * sg],     qa[1][ks], kh[0], kh[1]);
                    MMA_BF16(S[2 * sg + 1], qa[1][ks], kh[2], kh[3]);
                    MMA_BF16(S[2 * sg],     qa[1][ks], km[0], km[1]);
                    MMA_BF16(S[2 * sg + 1], qa[1][ks], km[2], km[3]);
                    MMA_BF16(S[2 * sg],     qa[2][ks], kh[0], kh[1]);
                    MMA_BF16(S[2 * sg + 1], qa[2][ks], kh[2], kh[3]);
                    MMA_BF16(S[2 * sg],     qa[0][ks], kl[0], kl[1]);
                    MMA_BF16(S[2 * sg + 1], qa[0][ks], kl[2], kl[3]);
                }
        }

        // ---- causal mask on diagonal tile
        if (tile == ntile - 1) {
            const int rl0 = warp * 16 + (lane >> 2);
#pragma unroll
            for (int nt = 0; nt < 8; nt++) {
                int cl = nt * 8 + (lane & 3) * 2;
#pragma unroll
                for (int e = 0; e < 4; e++) {
                    int col = cl + (e & 1);
                    int rl  = rl0 + (e >> 1) * 8;
                    if (col > rl) S[nt][e] = -1e30f;
                }
            }
        }

        // ---- per-row tile max + skip vote
        float tr0 = S[0][0], tr1 = S[0][2];
#pragma unroll
        for (int nt = 0; nt < 8; nt++) {
            tr0 = fmaxf(tr0, fmaxf(S[nt][0], S[nt][1]));
            tr1 = fmaxf(tr1, fmaxf(S[nt][2], S[nt][3]));
        }
        tr0 = fmaxf(tr0, __shfl_xor_sync(0xffffffffu, tr0, 1));
        tr0 = fmaxf(tr0, __shfl_xor_sync(0xffffffffu, tr0, 2));
        tr1 = fmaxf(tr1, __shfl_xor_sync(0xffffffffu, tr1, 1));
        tr1 = fmaxf(tr1, __shfl_xor_sync(0xffffffffu, tr1, 2));

        bool skip = (tr0 < m0 - 26.0f) && (tr1 < m1 - 26.0f);
        if (!__all_sync(0xffffffffu, skip)) {
            float mn0 = fmaxf(m0, tr0), mn1 = fmaxf(m1, tr1);
            float f0 = ex2f(m0 - mn0), f1 = ex2f(m1 - mn1);
            m0 = mn0; m1 = mn1;
            l0 *= f0;  l1 *= f1;
#pragma unroll
            for (int nt = 0; nt < 8; nt++) {
                O[nt][0] *= f0; O[nt][1] *= f0;
                O[nt][2] *= f1; O[nt][3] *= f1;
            }
            // exps (log2 domain)
#pragma unroll
            for (int nt = 0; nt < 8; nt++) {
                float p0 = ex2f(S[nt][0] - mn0);
                float p1 = ex2f(S[nt][1] - mn0);
                float p2 = ex2f(S[nt][2] - mn1);
                float p3 = ex2f(S[nt][3] - mn1);
                l0 += p0 + p1; l1 += p2 + p3;
                S[nt][0] = p0; S[nt][1] = p1; S[nt][2] = p2; S[nt][3] = p3;
            }
            // ---- PV: P 2-split x V 2-split, 3 products
            const uint32_t voff = (uint32_t)((lane & 15) * STRIDE + (lane >> 4) * 8) * 2u;
#pragma unroll
            for (int ks = 0; ks < 4; ks++) {
                uint32_t ah[4], al[4];
#pragma unroll
                for (int i = 0; i < 2; i++) {
                    int nt = 2 * ks + i;
                    uint32_t uh0; PACK_BF16X2(uh0, S[nt][0], S[nt][1]);
                    uint32_t uh1; PACK_BF16X2(uh1, S[nt][2], S[nt][3]);
                    float a0 = S[nt][0] - bf_lo(uh0), a1 = S[nt][1] - bf_hi(uh0);
                    float a2 = S[nt][2] - bf_lo(uh1), a3 = S[nt][3] - bf_hi(uh1);
                    uint32_t ul0; PACK_BF16X2(ul0, a0, a1);
                    uint32_t ul1; PACK_BF16X2(ul1, a2, a3);
                    ah[2 * i] = uh0; ah[2 * i + 1] = uh1;
                    al[2 * i] = ul0; al[2 * i + 1] = ul1;
                }
#pragma unroll
                for (int dg = 0; dg < 4; dg++) {
                    uint32_t base = (uint32_t)(ks * 16 * STRIDE + dg * 16) * 2u + voff;
                    uint32_t vh[4], vl[4];
                    LDMATRIX_X4_T(vh[0], vh[1], vh[2], vh[3], vh_p + base);
                    LDMATRIX_X4_T(vl[0], vl[1], vl[2], vl[3], vl_p + base);
                    MMA_BF16(O[2 * dg],     ah, vh[0], vh[1]);
                    MMA_BF16(O[2 * dg + 1], ah, vh[2], vh[3]);
                    MMA_BF16(O[2 * dg],     al, vh[0], vh[1]);
                    MMA_BF16(O[2 * dg + 1], al, vh[2], vh[3]);
                    MMA_BF16(O[2 * dg],     ah, vl[0], vl[1]);
                    MMA_BF16(O[2 * dg + 1], ah, vl[2], vl[3]);
                }
            }
        }
        __syncthreads();
    }

    // ---- epilogue
    l0 += __shfl_xor_sync(0xffffffffu, l0, 1);
    l0 += __shfl_xor_sync(0xffffffffu, l0, 2);
    l1 += __shfl_xor_sync(0xffffffffu, l1, 1);
    l1 += __shfl_xor_sync(0xffffffffu, l1, 2);
    float inv0 = 1.0f / l0, inv1 = 1.0f / l1;

    const size_t gr0 = (size_t)n * Lq + q0 + warp * 16 + (lane >> 2);
#pragma unroll
    for (int nt = 0; nt < 8; nt++) {
        int col = nt * 8 + (lane & 3) * 2;
        float2 v0 = {O[nt][0] * inv0, O[nt][1] * inv0};
        float2 v1 = {O[nt][2] * inv1, O[nt][3] * inv1};
        *(float2*)(out + gr0 * Dh + col)       = v0;
        *(float2*)(out + (gr0 + 8) * Dh + col) = v1;
    }
}

extern "C" void kernel_launch(void* const* d_in, const int* in_sizes, int n_in,
                              void* d_out, int out_size) {
    const float* q  = (const float*)d_in[0];
    const float* k  = (const float*)d_in[1];
    const float* v  = (const float*)d_in[2];
    const float* Wq = (const float*)d_in[3];
    const float* Wk = (const float*)d_in[4];
    const float* Wv = (const float*)d_in[5];
    float* out = (float*)d_out;

    float* qh;
    cudaGetSymbolAddress((void**)&qh, g_qh);

    const int smem_attn = 2 * NPLANE * PLANE_B;   // 92160 B
    cudaFuncSetAttribute(attn_mma, cudaFuncAttributeMaxDynamicSharedMemorySize, smem_attn);

    dim3 pgrid((Nb * Lq) / 128, 3);
    proj_mma<<<pgrid, 256>>>(q, k, v, Wq, Wk, Wv, qh);

    dim3 grid(32, Nb);
    attn_mma<<<grid, 128, smem_attn>>>(out);
}